// round 8
// baseline (speedup 1.0000x reference)
#include <cuda_runtime.h>

#define BATCH 2048
#define SEQ   128
#define F     512
#define NACT  128
#define GN_EPS 1e-5f

// ---------------- scratch (no allocations allowed) ----------------
__device__ float g_p_avg[BATCH * F];
__device__ float g_e_avg[BATCH * F];
__device__ float g_p_embed[BATCH * F];
__device__ int   g_off[NACT + 1];
__device__ int   g_perm[BATCH];

// ---------------- K1: masked mean over seq + GroupNorm(1,1) ----------------
__global__ void k_reduce_gn(const float* __restrict__ pre,
                            const float* __restrict__ eff,
                            const float* __restrict__ gamma,
                            const float* __restrict__ beta)
{
    const int b = blockIdx.x;
    const float* src = (blockIdx.y == 0) ? pre : eff;
    float* dst       = (blockIdx.y == 0) ? g_p_avg : g_e_avg;

    const int t = threadIdx.x;  // 0..127
    const float4* row = (const float4*)(src + (size_t)b * SEQ * F);

    float4 sum = make_float4(0.f, 0.f, 0.f, 0.f);
    int cx = 0, cy = 0, cz = 0, cw = 0;

    #pragma unroll 8
    for (int s = 0; s < SEQ; s++) {
        float4 v = row[s * (F / 4) + t];
        sum.x += v.x; sum.y += v.y; sum.z += v.z; sum.w += v.w;
        cx += (v.x != 0.0f); cy += (v.y != 0.0f);
        cz += (v.z != 0.0f); cw += (v.w != 0.0f);
    }

    float4 m;
    m.x = sum.x / (float)cx;
    m.y = sum.y / (float)cy;
    m.z = sum.z / (float)cz;
    m.w = sum.w / (float)cw;

    float ls = m.x + m.y + m.z + m.w;
    float lq = m.x * m.x + m.y * m.y + m.z * m.z + m.w * m.w;

    __shared__ float s1[128], s2[128];
    s1[t] = ls; s2[t] = lq;
    __syncthreads();
    #pragma unroll
    for (int o = 64; o > 0; o >>= 1) {
        if (t < o) { s1[t] += s1[t + o]; s2[t] += s2[t + o]; }
        __syncthreads();
    }
    const float mu  = s1[0] * (1.0f / F);
    const float var = s2[0] * (1.0f / F) - mu * mu;
    const float r   = rsqrtf(var + GN_EPS) * gamma[0];
    const float be  = beta[0];

    float4 o4;
    o4.x = (m.x - mu) * r + be;
    o4.y = (m.y - mu) * r + be;
    o4.z = (m.z - mu) * r + be;
    o4.w = (m.w - mu) * r + be;
    ((float4*)(dst + (size_t)b * F))[t] = o4;
}

// ---------------- K2: group batch indices by action ----------------
__global__ void k_group(const int* __restrict__ action)
{
    __shared__ int s_cnt[NACT];
    __shared__ int s_cur[NACT];
    const int t = threadIdx.x;
    if (t < NACT) s_cnt[t] = 0;
    __syncthreads();
    for (int i = t; i < BATCH; i += 256)
        atomicAdd(&s_cnt[action[i]], 1);
    __syncthreads();
    if (t == 0) {
        int acc = 0;
        for (int a = 0; a < NACT; a++) {
            g_off[a] = acc; s_cur[a] = acc; acc += s_cnt[a];
        }
        g_off[NACT] = acc;
    }
    __syncthreads();
    for (int i = t; i < BATCH; i += 256) {
        int pos = atomicAdd(&s_cur[action[i]], 1);
        g_perm[pos] = i;
    }
}

// ---------------- K3: embed GEMMs ----------------
// grid (F/64, BATCH/128, 2), 256 threads. Tile 128m x 64i, Kt=16, 8x4 microtile.
__global__ void __launch_bounds__(256)
k_embed(const float* __restrict__ pw, const float* __restrict__ pb,
        const float* __restrict__ ew, const float* __restrict__ eb,
        float* __restrict__ dout)
{
    const float* A; const float* Wt; const float* bias; float* C;
    if (blockIdx.z == 0) { A = g_p_avg; Wt = pw; bias = pb; C = g_p_embed; }
    else                 { A = g_e_avg; Wt = ew; bias = eb; C = dout + (size_t)BATCH * F; }

    const int i0 = blockIdx.x * 64;
    const int b0 = blockIdx.y * 128;

    __shared__ float As[16][128];
    __shared__ float Bs[16][64];

    const int t  = threadIdx.x;
    const int tx = t & 15;
    const int ty = t >> 4;

    const int lr = t >> 2;
    const int lk = (t & 3) * 4;

    float acc[8][4];
    #pragma unroll
    for (int r = 0; r < 8; r++)
        #pragma unroll
        for (int c = 0; c < 4; c++) acc[r][c] = 0.f;

    float4 a0 = *(const float4*)(A  + (size_t)(b0 + lr)      * F + lk);
    float4 a1 = *(const float4*)(A  + (size_t)(b0 + lr + 64) * F + lk);
    float4 bv = *(const float4*)(Wt + (size_t)(i0 + lr)      * F + lk);

    for (int k0 = 0; k0 < F; k0 += 16) {
        As[lk + 0][lr]      = a0.x; As[lk + 1][lr]      = a0.y;
        As[lk + 2][lr]      = a0.z; As[lk + 3][lr]      = a0.w;
        As[lk + 0][lr + 64] = a1.x; As[lk + 1][lr + 64] = a1.y;
        As[lk + 2][lr + 64] = a1.z; As[lk + 3][lr + 64] = a1.w;
        Bs[lk + 0][lr] = bv.x; Bs[lk + 1][lr] = bv.y;
        Bs[lk + 2][lr] = bv.z; Bs[lk + 3][lr] = bv.w;
        __syncthreads();

        if (k0 + 16 < F) {
            a0 = *(const float4*)(A  + (size_t)(b0 + lr)      * F + k0 + 16 + lk);
            a1 = *(const float4*)(A  + (size_t)(b0 + lr + 64) * F + k0 + 16 + lk);
            bv = *(const float4*)(Wt + (size_t)(i0 + lr)      * F + k0 + 16 + lk);
        }

        #pragma unroll
        for (int kk = 0; kk < 16; kk++) {
            float4 ra0 = *(const float4*)&As[kk][ty * 8];
            float4 ra1 = *(const float4*)&As[kk][ty * 8 + 4];
            float4 rb  = *(const float4*)&Bs[kk][tx * 4];
            float am[8] = { ra0.x, ra0.y, ra0.z, ra0.w, ra1.x, ra1.y, ra1.z, ra1.w };
            float bn[4] = { rb.x, rb.y, rb.z, rb.w };
            #pragma unroll
            for (int r = 0; r < 8; r++)
                #pragma unroll
                for (int c = 0; c < 4; c++)
                    acc[r][c] += am[r] * bn[c];
        }
        __syncthreads();
    }

    float bsv[4];
    #pragma unroll
    for (int c = 0; c < 4; c++) bsv[c] = bias[i0 + tx * 4 + c];

    #pragma unroll
    for (int r = 0; r < 8; r++) {
        float4 o;
        o.x = acc[r][0] + bsv[0];
        o.y = acc[r][1] + bsv[1];
        o.z = acc[r][2] + bsv[2];
        o.w = acc[r][3] + bsv[3];
        *(float4*)(C + (size_t)(b0 + ty * 8 + r) * F + i0 + tx * 4) = o;
    }
}

// ---------------- K4: per-action gather GEMM ----------------
// out[b][i] = sum_j W[a][i][j] * p_embed[b][j]
// grid (NACT, 4, 2), 128 threads. CTA tile 8m x 256i, micro 2m x 8i.
// As: 8 P rows (padded). Bs: double-buffered [2][8][256] W chunks.
#define FP (F + 4)
__global__ void __launch_bounds__(128)
k_action(const float* __restrict__ W, float* __restrict__ dout)
{
    const int a   = blockIdx.x;
    const int z   = blockIdx.y;        // m-phase 0..3 (8 rows each, step 32)
    const int ih  = blockIdx.z;        // i half
    const int i0  = ih * 256;
    const int beg = g_off[a];
    const int n   = g_off[a + 1] - beg;
    if (z * 8 >= n) return;

    __shared__ float As[8][FP];        // P rows [m][k]     16.5 KB
    __shared__ float Bs[2][8][256];    // W chunks [k][i]   16 KB

    const int t  = threadIdx.x;        // 0..127
    const int ti = t & 31;             // i-group
    const int tm = t >> 5;             // m-group: rows tm*2, tm*2+1
    const int ia = ti * 4;             // i quad A
    const int ib = ti * 4 + 128;       // i quad B

    const float* Wa = W + (size_t)a * F * F + (size_t)i0 * F;

    for (int m0 = z * 8; m0 < n; m0 += 32) {
        // ---- stage 8 P rows (row-major) ----
        {
            const int m  = t >> 4;             // 0..7
            const int c4 = t & 15;             // float4 lane
            const int mi = (m0 + m < n) ? (m0 + m) : m0;   // clamp; never written out
            const float4* src = (const float4*)(g_p_embed + (size_t)g_perm[beg + mi] * F);
            float4* dstr = (float4*)&As[m][0];
            #pragma unroll
            for (int j = 0; j < 8; j++)
                dstr[c4 + j * 16] = src[c4 + j * 16];
        }

        float acc[2][8];
        #pragma unroll
        for (int r = 0; r < 2; r++)
            #pragma unroll
            for (int c = 0; c < 8; c++) acc[r][c] = 0.f;

        // prefetch + store W chunk 0 into buffer 0
        {
            float4 w00 = *(const float4*)(Wa + (size_t)t         * F + 0);
            float4 w01 = *(const float4*)(Wa + (size_t)t         * F + 4);
            float4 w10 = *(const float4*)(Wa + (size_t)(t + 128) * F + 0);
            float4 w11 = *(const float4*)(Wa + (size_t)(t + 128) * F + 4);
            Bs[0][0][t] = w00.x; Bs[0][1][t] = w00.y; Bs[0][2][t] = w00.z; Bs[0][3][t] = w00.w;
            Bs[0][4][t] = w01.x; Bs[0][5][t] = w01.y; Bs[0][6][t] = w01.z; Bs[0][7][t] = w01.w;
            Bs[0][0][t+128] = w10.x; Bs[0][1][t+128] = w10.y; Bs[0][2][t+128] = w10.z; Bs[0][3][t+128] = w10.w;
            Bs[0][4][t+128] = w11.x; Bs[0][5][t+128] = w11.y; Bs[0][6][t+128] = w11.z; Bs[0][7][t+128] = w11.w;
        }
        __syncthreads();

        for (int c = 0; c < F / 8; c++) {
            const int cur = c & 1;
            const int kb  = c * 8;

            // prefetch next chunk
            float4 w00, w01, w10, w11;
            const bool more = (c + 1 < F / 8);
            if (more) {
                const int kn = kb + 8;
                w00 = *(const float4*)(Wa + (size_t)t         * F + kn);
                w01 = *(const float4*)(Wa + (size_t)t         * F + kn + 4);
                w10 = *(const float4*)(Wa + (size_t)(t + 128) * F + kn);
                w11 = *(const float4*)(Wa + (size_t)(t + 128) * F + kn + 4);
            }

            // compute on current buffer
            #pragma unroll
            for (int kk = 0; kk < 8; kk++) {
                const float a0v = As[tm * 2 + 0][kb + kk];
                const float a1v = As[tm * 2 + 1][kb + kk];
                const float4 b0 = *(const float4*)&Bs[cur][kk][ia];
                const float4 b1 = *(const float4*)&Bs[cur][kk][ib];
                acc[0][0] += a0v * b0.x; acc[0][1] += a0v * b0.y;
                acc[0][2] += a0v * b0.z; acc[0][3] += a0v * b0.w;
                acc[0][4] += a0v * b1.x; acc[0][5] += a0v * b1.y;
                acc[0][6] += a0v * b1.z; acc[0][7] += a0v * b1.w;
                acc[1][0] += a1v * b0.x; acc[1][1] += a1v * b0.y;
                acc[1][2] += a1v * b0.z; acc[1][3] += a1v * b0.w;
                acc[1][4] += a1v * b1.x; acc[1][5] += a1v * b1.y;
                acc[1][6] += a1v * b1.z; acc[1][7] += a1v * b1.w;
            }

            // store next chunk into other buffer
            if (more) {
                const int nb = cur ^ 1;
                Bs[nb][0][t] = w00.x; Bs[nb][1][t] = w00.y; Bs[nb][2][t] = w00.z; Bs[nb][3][t] = w00.w;
                Bs[nb][4][t] = w01.x; Bs[nb][5][t] = w01.y; Bs[nb][6][t] = w01.z; Bs[nb][7][t] = w01.w;
                Bs[nb][0][t+128] = w10.x; Bs[nb][1][t+128] = w10.y; Bs[nb][2][t+128] = w10.z; Bs[nb][3][t+128] = w10.w;
                Bs[nb][4][t+128] = w11.x; Bs[nb][5][t+128] = w11.y; Bs[nb][6][t+128] = w11.z; Bs[nb][7][t+128] = w11.w;
            }
            __syncthreads();
        }

        // write out 2 m rows x (2 x 4i)
        #pragma unroll
        for (int r = 0; r < 2; r++) {
            const int m = m0 + tm * 2 + r;
            if (m < n) {
                const int orow = g_perm[beg + m];
                *(float4*)(dout + (size_t)orow * F + i0 + ia) =
                    make_float4(acc[r][0], acc[r][1], acc[r][2], acc[r][3]);
                *(float4*)(dout + (size_t)orow * F + i0 + ib) =
                    make_float4(acc[r][4], acc[r][5], acc[r][6], acc[r][7]);
            }
        }
        __syncthreads();   // protect As before restage
    }
}

// ---------------- launch ----------------
extern "C" void kernel_launch(void* const* d_in, const int* in_sizes, int n_in,
                              void* d_out, int out_size)
{
    const float* pre   = (const float*)d_in[0];
    const float* eff   = (const float*)d_in[1];
    const int*   act   = (const int*)  d_in[2];
    const float* W     = (const float*)d_in[3];
    const float* pw    = (const float*)d_in[4];
    const float* pb    = (const float*)d_in[5];
    const float* ew    = (const float*)d_in[6];
    const float* eb    = (const float*)d_in[7];
    const float* gamma = (const float*)d_in[8];
    const float* beta  = (const float*)d_in[9];
    float* out = (float*)d_out;

    k_group<<<1, 256>>>(act);
    k_reduce_gn<<<dim3(BATCH, 2), 128>>>(pre, eff, gamma, beta);
    k_embed<<<dim3(F / 64, BATCH / 128, 2), 256>>>(pw, pb, ew, eb, out);
    k_action<<<dim3(NACT, 4, 2), 128>>>(W, out);
}

// round 10
// speedup vs baseline: 1.5855x; 1.5855x over previous
#include <cuda_runtime.h>

#define BATCH 2048
#define SEQ   128
#define F     512
#define NACT  128
#define GN_EPS 1e-5f

// ---------------- scratch (no allocations allowed) ----------------
__device__ float g_p_avg[BATCH * F];
__device__ float g_e_avg[BATCH * F];
__device__ float g_p_embed[BATCH * F];
__device__ int   g_off[NACT + 1];
__device__ int   g_perm[BATCH];

// ---------------- K0: zero first half of output (atomic target) ----------------
__global__ void k_zero(float* __restrict__ out)
{
    ((float4*)out)[blockIdx.x * 256 + threadIdx.x] =
        make_float4(0.f, 0.f, 0.f, 0.f);
}

// ---------------- K1: masked mean over seq + GroupNorm(1,1) ----------------
__global__ void k_reduce_gn(const float* __restrict__ pre,
                            const float* __restrict__ eff,
                            const float* __restrict__ gamma,
                            const float* __restrict__ beta)
{
    const int b = blockIdx.x;
    const float* src = (blockIdx.y == 0) ? pre : eff;
    float* dst       = (blockIdx.y == 0) ? g_p_avg : g_e_avg;

    const int t = threadIdx.x;  // 0..127
    const float4* row = (const float4*)(src + (size_t)b * SEQ * F);

    float4 sum = make_float4(0.f, 0.f, 0.f, 0.f);
    int cx = 0, cy = 0, cz = 0, cw = 0;

    #pragma unroll 8
    for (int s = 0; s < SEQ; s++) {
        float4 v = row[s * (F / 4) + t];
        sum.x += v.x; sum.y += v.y; sum.z += v.z; sum.w += v.w;
        cx += (v.x != 0.0f); cy += (v.y != 0.0f);
        cz += (v.z != 0.0f); cw += (v.w != 0.0f);
    }

    float4 m;
    m.x = sum.x / (float)cx;
    m.y = sum.y / (float)cy;
    m.z = sum.z / (float)cz;
    m.w = sum.w / (float)cw;

    float ls = m.x + m.y + m.z + m.w;
    float lq = m.x * m.x + m.y * m.y + m.z * m.z + m.w * m.w;

    __shared__ float s1[128], s2[128];
    s1[t] = ls; s2[t] = lq;
    __syncthreads();
    #pragma unroll
    for (int o = 64; o > 0; o >>= 1) {
        if (t < o) { s1[t] += s1[t + o]; s2[t] += s2[t + o]; }
        __syncthreads();
    }
    const float mu  = s1[0] * (1.0f / F);
    const float var = s2[0] * (1.0f / F) - mu * mu;
    const float r   = rsqrtf(var + GN_EPS) * gamma[0];
    const float be  = beta[0];

    float4 o4;
    o4.x = (m.x - mu) * r + be;
    o4.y = (m.y - mu) * r + be;
    o4.z = (m.z - mu) * r + be;
    o4.w = (m.w - mu) * r + be;
    ((float4*)(dst + (size_t)b * F))[t] = o4;
}

// ---------------- K2: group batch indices by action ----------------
__global__ void k_group(const int* __restrict__ action)
{
    __shared__ int s_cnt[NACT];
    __shared__ int s_cur[NACT];
    const int t = threadIdx.x;
    if (t < NACT) s_cnt[t] = 0;
    __syncthreads();
    for (int i = t; i < BATCH; i += 256)
        atomicAdd(&s_cnt[action[i]], 1);
    __syncthreads();
    if (t == 0) {
        int acc = 0;
        for (int a = 0; a < NACT; a++) {
            g_off[a] = acc; s_cur[a] = acc; acc += s_cnt[a];
        }
        g_off[NACT] = acc;
    }
    __syncthreads();
    for (int i = t; i < BATCH; i += 256) {
        int pos = atomicAdd(&s_cur[action[i]], 1);
        g_perm[pos] = i;
    }
}

// ---------------- K3: embed GEMMs ----------------
// grid (F/64, BATCH/128, 2), 256 threads. Tile 128m x 64i, Kt=16, 8x4 microtile.
__global__ void __launch_bounds__(256)
k_embed(const float* __restrict__ pw, const float* __restrict__ pb,
        const float* __restrict__ ew, const float* __restrict__ eb,
        float* __restrict__ dout)
{
    const float* A; const float* Wt; const float* bias; float* C;
    if (blockIdx.z == 0) { A = g_p_avg; Wt = pw; bias = pb; C = g_p_embed; }
    else                 { A = g_e_avg; Wt = ew; bias = eb; C = dout + (size_t)BATCH * F; }

    const int i0 = blockIdx.x * 64;
    const int b0 = blockIdx.y * 128;

    __shared__ float As[16][128];
    __shared__ float Bs[16][64];

    const int t  = threadIdx.x;
    const int tx = t & 15;
    const int ty = t >> 4;

    const int lr = t >> 2;
    const int lk = (t & 3) * 4;

    float acc[8][4];
    #pragma unroll
    for (int r = 0; r < 8; r++)
        #pragma unroll
        for (int c = 0; c < 4; c++) acc[r][c] = 0.f;

    float4 a0 = *(const float4*)(A  + (size_t)(b0 + lr)      * F + lk);
    float4 a1 = *(const float4*)(A  + (size_t)(b0 + lr + 64) * F + lk);
    float4 bv = *(const float4*)(Wt + (size_t)(i0 + lr)      * F + lk);

    for (int k0 = 0; k0 < F; k0 += 16) {
        As[lk + 0][lr]      = a0.x; As[lk + 1][lr]      = a0.y;
        As[lk + 2][lr]      = a0.z; As[lk + 3][lr]      = a0.w;
        As[lk + 0][lr + 64] = a1.x; As[lk + 1][lr + 64] = a1.y;
        As[lk + 2][lr + 64] = a1.z; As[lk + 3][lr + 64] = a1.w;
        Bs[lk + 0][lr] = bv.x; Bs[lk + 1][lr] = bv.y;
        Bs[lk + 2][lr] = bv.z; Bs[lk + 3][lr] = bv.w;
        __syncthreads();

        if (k0 + 16 < F) {
            a0 = *(const float4*)(A  + (size_t)(b0 + lr)      * F + k0 + 16 + lk);
            a1 = *(const float4*)(A  + (size_t)(b0 + lr + 64) * F + k0 + 16 + lk);
            bv = *(const float4*)(Wt + (size_t)(i0 + lr)      * F + k0 + 16 + lk);
        }

        #pragma unroll
        for (int kk = 0; kk < 16; kk++) {
            float4 ra0 = *(const float4*)&As[kk][ty * 8];
            float4 ra1 = *(const float4*)&As[kk][ty * 8 + 4];
            float4 rb  = *(const float4*)&Bs[kk][tx * 4];
            float am[8] = { ra0.x, ra0.y, ra0.z, ra0.w, ra1.x, ra1.y, ra1.z, ra1.w };
            float bn[4] = { rb.x, rb.y, rb.z, rb.w };
            #pragma unroll
            for (int r = 0; r < 8; r++)
                #pragma unroll
                for (int c = 0; c < 4; c++)
                    acc[r][c] += am[r] * bn[c];
        }
        __syncthreads();
    }

    float bsv[4];
    #pragma unroll
    for (int c = 0; c < 4; c++) bsv[c] = bias[i0 + tx * 4 + c];

    #pragma unroll
    for (int r = 0; r < 8; r++) {
        float4 o;
        o.x = acc[r][0] + bsv[0];
        o.y = acc[r][1] + bsv[1];
        o.z = acc[r][2] + bsv[2];
        o.w = acc[r][3] + bsv[3];
        *(float4*)(C + (size_t)(b0 + ty * 8 + r) * F + i0 + tx * 4) = o;
    }
}

// ---------------- K4: per-action gather GEMM, K-split + atomics ----------------
// out[b][i] += sum_{j in kc} W[a][i][j] * p_embed[b][j]
// grid (NACT, 4 kchunks, 2 ihalves), 256 threads.
// CTA tile: 256i x 16m x 128k. Micro 2m x 8i (16 accs).
#define KC 128               // K per CTA
__global__ void __launch_bounds__(256)
k_action(const float* __restrict__ W, float* __restrict__ dout)
{
    const int a   = blockIdx.x;
    const int kc  = blockIdx.y;        // k chunk 0..3
    const int ih  = blockIdx.z;        // i half
    const int i0  = ih * 256;
    const int k0g = kc * KC;
    const int beg = g_off[a];
    const int n   = g_off[a + 1] - beg;

    __shared__ float As[16][KC + 4];   // P rows [m][k_local]  8.25 KB
    __shared__ float Bs[8][256];       // W chunk [k][i]       8 KB

    const int t  = threadIdx.x;        // 0..255
    const int ti = t & 31;             // i-group: cols ti*4 and ti*4+128
    const int tm = t >> 5;             // m-group 0..7: rows tm*2, tm*2+1
    const int ia = ti * 4;
    const int ib = ti * 4 + 128;

    // W slice base: rows [i0, i0+256), cols [k0g, k0g+KC)
    const float* Wa = W + (size_t)a * F * F + (size_t)i0 * F + k0g;

    for (int m0 = 0; m0 < n; m0 += 16) {
        // ---- stage 16 P rows (local K window), row-major ----
        {
            const int m  = t >> 4;             // 0..15
            const int c4 = t & 15;             // float4 lane 0..15 (two per row)
            const int mi = (m0 + m < n) ? (m0 + m) : m0;   // clamp; never written out
            const float* src = g_p_embed + (size_t)g_perm[beg + mi] * F + k0g;
            float4 v0 = *(const float4*)(src + c4 * 4);
            float4 v1 = *(const float4*)(src + (c4 + 16) * 4);
            *(float4*)&As[m][c4 * 4]        = v0;
            *(float4*)&As[m][(c4 + 16) * 4] = v1;
        }

        float acc[2][8];
        #pragma unroll
        for (int r = 0; r < 2; r++)
            #pragma unroll
            for (int c = 0; c < 8; c++) acc[r][c] = 0.f;

        // prefetch W chunk 0: row t, k 0..7 of local window
        float4 w0 = *(const float4*)(Wa + (size_t)t * F + 0);
        float4 w1 = *(const float4*)(Wa + (size_t)t * F + 4);
        __syncthreads();   // As staged

        for (int c = 0; c < KC / 8; c++) {
            // store staged W chunk (transposed to [k][i])
            Bs[0][t] = w0.x; Bs[1][t] = w0.y; Bs[2][t] = w0.z; Bs[3][t] = w0.w;
            Bs[4][t] = w1.x; Bs[5][t] = w1.y; Bs[6][t] = w1.z; Bs[7][t] = w1.w;
            __syncthreads();

            if (c + 1 < KC / 8) {
                const int kn = (c + 1) * 8;
                w0 = *(const float4*)(Wa + (size_t)t * F + kn);
                w1 = *(const float4*)(Wa + (size_t)t * F + kn + 4);
            }

            const int kb = c * 8;
            #pragma unroll
            for (int kk = 0; kk < 8; kk++) {
                const float a0v = As[tm * 2 + 0][kb + kk];
                const float a1v = As[tm * 2 + 1][kb + kk];
                const float4 b0 = *(const float4*)&Bs[kk][ia];
                const float4 b1 = *(const float4*)&Bs[kk][ib];
                acc[0][0] += a0v * b0.x; acc[0][1] += a0v * b0.y;
                acc[0][2] += a0v * b0.z; acc[0][3] += a0v * b0.w;
                acc[0][4] += a0v * b1.x; acc[0][5] += a0v * b1.y;
                acc[0][6] += a0v * b1.z; acc[0][7] += a0v * b1.w;
                acc[1][0] += a1v * b0.x; acc[1][1] += a1v * b0.y;
                acc[1][2] += a1v * b0.z; acc[1][3] += a1v * b0.w;
                acc[1][4] += a1v * b1.x; acc[1][5] += a1v * b1.y;
                acc[1][6] += a1v * b1.z; acc[1][7] += a1v * b1.w;
            }
            __syncthreads();
        }

        // accumulate partials into output
        #pragma unroll
        for (int r = 0; r < 2; r++) {
            const int m = m0 + tm * 2 + r;
            if (m < n) {
                float* obase = dout + (size_t)g_perm[beg + m] * F + i0;
                atomicAdd(obase + ia + 0, acc[r][0]);
                atomicAdd(obase + ia + 1, acc[r][1]);
                atomicAdd(obase + ia + 2, acc[r][2]);
                atomicAdd(obase + ia + 3, acc[r][3]);
                atomicAdd(obase + ib + 0, acc[r][4]);
                atomicAdd(obase + ib + 1, acc[r][5]);
                atomicAdd(obase + ib + 2, acc[r][6]);
                atomicAdd(obase + ib + 3, acc[r][7]);
            }
        }
    }
}

// ---------------- launch ----------------
extern "C" void kernel_launch(void* const* d_in, const int* in_sizes, int n_in,
                              void* d_out, int out_size)
{
    const float* pre   = (const float*)d_in[0];
    const float* eff   = (const float*)d_in[1];
    const int*   act   = (const int*)  d_in[2];
    const float* W     = (const float*)d_in[3];
    const float* pw    = (const float*)d_in[4];
    const float* pb    = (const float*)d_in[5];
    const float* ew    = (const float*)d_in[6];
    const float* eb    = (const float*)d_in[7];
    const float* gamma = (const float*)d_in[8];
    const float* beta  = (const float*)d_in[9];
    float* out = (float*)d_out;

    k_zero<<<(BATCH * F) / (256 * 4), 256>>>(out);   // zero first half (atomic target)
    k_group<<<1, 256>>>(act);
    k_reduce_gn<<<dim3(BATCH, 2), 128>>>(pre, eff, gamma, beta);
    k_embed<<<dim3(F / 64, BATCH / 128, 2), 256>>>(pw, pb, ew, eb, out);
    k_action<<<dim3(NACT, 4, 2), 256>>>(W, out);
}

// round 11
// speedup vs baseline: 1.5961x; 1.0067x over previous
#include <cuda_runtime.h>

#define BATCH 2048
#define SEQ   128
#define F     512
#define NACT  128
#define GN_EPS 1e-5f

// ---------------- scratch (no allocations allowed) ----------------
__device__ float g_p_avg[BATCH * F];
__device__ float g_e_avg[BATCH * F];
__device__ float g_p_embed[BATCH * F];
__device__ int   g_off[NACT + 1];
__device__ int   g_perm[BATCH];

// ---------------- K0: zero atomic targets ----------------
// zeroes d_out (8 MB) and g_p_embed (4 MB)
__global__ void k_zero(float* __restrict__ out)
{
    const int idx = blockIdx.x * 256 + threadIdx.x;
    const int n_out4 = (BATCH * F * 2) / 4;
    if (idx < n_out4)
        ((float4*)out)[idx] = make_float4(0.f, 0.f, 0.f, 0.f);
    else
        ((float4*)g_p_embed)[idx - n_out4] = make_float4(0.f, 0.f, 0.f, 0.f);
}

// ---------------- K1: masked mean over seq + GroupNorm(1,1) ----------------
__global__ void k_reduce_gn(const float* __restrict__ pre,
                            const float* __restrict__ eff,
                            const float* __restrict__ gamma,
                            const float* __restrict__ beta)
{
    const int b = blockIdx.x;
    const float* src = (blockIdx.y == 0) ? pre : eff;
    float* dst       = (blockIdx.y == 0) ? g_p_avg : g_e_avg;

    const int t = threadIdx.x;  // 0..127
    const float4* row = (const float4*)(src + (size_t)b * SEQ * F);

    float4 sum = make_float4(0.f, 0.f, 0.f, 0.f);
    int cx = 0, cy = 0, cz = 0, cw = 0;

    #pragma unroll 8
    for (int s = 0; s < SEQ; s++) {
        float4 v = row[s * (F / 4) + t];
        sum.x += v.x; sum.y += v.y; sum.z += v.z; sum.w += v.w;
        cx += (v.x != 0.0f); cy += (v.y != 0.0f);
        cz += (v.z != 0.0f); cw += (v.w != 0.0f);
    }

    float4 m;
    m.x = sum.x / (float)cx;
    m.y = sum.y / (float)cy;
    m.z = sum.z / (float)cz;
    m.w = sum.w / (float)cw;

    float ls = m.x + m.y + m.z + m.w;
    float lq = m.x * m.x + m.y * m.y + m.z * m.z + m.w * m.w;

    __shared__ float s1[128], s2[128];
    s1[t] = ls; s2[t] = lq;
    __syncthreads();
    #pragma unroll
    for (int o = 64; o > 0; o >>= 1) {
        if (t < o) { s1[t] += s1[t + o]; s2[t] += s2[t + o]; }
        __syncthreads();
    }
    const float mu  = s1[0] * (1.0f / F);
    const float var = s2[0] * (1.0f / F) - mu * mu;
    const float r   = rsqrtf(var + GN_EPS) * gamma[0];
    const float be  = beta[0];

    float4 o4;
    o4.x = (m.x - mu) * r + be;
    o4.y = (m.y - mu) * r + be;
    o4.z = (m.z - mu) * r + be;
    o4.w = (m.w - mu) * r + be;
    ((float4*)(dst + (size_t)b * F))[t] = o4;
}

// ---------------- K2: group batch indices by action ----------------
__global__ void k_group(const int* __restrict__ action)
{
    __shared__ int s_cnt[NACT];
    __shared__ int s_cur[NACT];
    const int t = threadIdx.x;
    if (t < NACT) s_cnt[t] = 0;
    __syncthreads();
    for (int i = t; i < BATCH; i += 256)
        atomicAdd(&s_cnt[action[i]], 1);
    __syncthreads();
    if (t == 0) {
        int acc = 0;
        for (int a = 0; a < NACT; a++) {
            g_off[a] = acc; s_cur[a] = acc; acc += s_cnt[a];
        }
        g_off[NACT] = acc;
    }
    __syncthreads();
    for (int i = t; i < BATCH; i += 256) {
        int pos = atomicAdd(&s_cur[action[i]], 1);
        g_perm[pos] = i;
    }
}

// ---------------- K3: embed GEMMs, K-split 2 + atomics ----------------
// C[b][i] += partial dot(A[b, kc*256 : +256], Wt[i, ...]) (+ bias on kc==0)
// grid (F/64, BATCH/128, 4), 256 threads. z = src*2 + kc.
// Tile 128m x 64i, Kt=16, 8x4 microtile.
#define EKC 256
__global__ void __launch_bounds__(256)
k_embed(const float* __restrict__ pw, const float* __restrict__ pb,
        const float* __restrict__ ew, const float* __restrict__ eb,
        float* __restrict__ dout)
{
    const int srcsel = blockIdx.z >> 1;
    const int kc     = blockIdx.z & 1;
    const int k0g    = kc * EKC;

    const float* A; const float* Wt; const float* bias; float* C;
    if (srcsel == 0) { A = g_p_avg; Wt = pw; bias = pb; C = g_p_embed; }
    else             { A = g_e_avg; Wt = ew; bias = eb; C = dout + (size_t)BATCH * F; }

    const int i0 = blockIdx.x * 64;
    const int b0 = blockIdx.y * 128;

    __shared__ float As[16][128];
    __shared__ float Bs[16][64];

    const int t  = threadIdx.x;
    const int tx = t & 15;
    const int ty = t >> 4;

    const int lr = t >> 2;
    const int lk = (t & 3) * 4;

    float acc[8][4];
    #pragma unroll
    for (int r = 0; r < 8; r++)
        #pragma unroll
        for (int c = 0; c < 4; c++) acc[r][c] = 0.f;

    float4 a0 = *(const float4*)(A  + (size_t)(b0 + lr)      * F + k0g + lk);
    float4 a1 = *(const float4*)(A  + (size_t)(b0 + lr + 64) * F + k0g + lk);
    float4 bv = *(const float4*)(Wt + (size_t)(i0 + lr)      * F + k0g + lk);

    for (int k0 = 0; k0 < EKC; k0 += 16) {
        As[lk + 0][lr]      = a0.x; As[lk + 1][lr]      = a0.y;
        As[lk + 2][lr]      = a0.z; As[lk + 3][lr]      = a0.w;
        As[lk + 0][lr + 64] = a1.x; As[lk + 1][lr + 64] = a1.y;
        As[lk + 2][lr + 64] = a1.z; As[lk + 3][lr + 64] = a1.w;
        Bs[lk + 0][lr] = bv.x; Bs[lk + 1][lr] = bv.y;
        Bs[lk + 2][lr] = bv.z; Bs[lk + 3][lr] = bv.w;
        __syncthreads();

        if (k0 + 16 < EKC) {
            a0 = *(const float4*)(A  + (size_t)(b0 + lr)      * F + k0g + k0 + 16 + lk);
            a1 = *(const float4*)(A  + (size_t)(b0 + lr + 64) * F + k0g + k0 + 16 + lk);
            bv = *(const float4*)(Wt + (size_t)(i0 + lr)      * F + k0g + k0 + 16 + lk);
        }

        #pragma unroll
        for (int kk = 0; kk < 16; kk++) {
            float4 ra0 = *(const float4*)&As[kk][ty * 8];
            float4 ra1 = *(const float4*)&As[kk][ty * 8 + 4];
            float4 rb  = *(const float4*)&Bs[kk][tx * 4];
            float am[8] = { ra0.x, ra0.y, ra0.z, ra0.w, ra1.x, ra1.y, ra1.z, ra1.w };
            float bn[4] = { rb.x, rb.y, rb.z, rb.w };
            #pragma unroll
            for (int r = 0; r < 8; r++)
                #pragma unroll
                for (int c = 0; c < 4; c++)
                    acc[r][c] += am[r] * bn[c];
        }
        __syncthreads();
    }

    float bsv[4] = { 0.f, 0.f, 0.f, 0.f };
    if (kc == 0) {
        #pragma unroll
        for (int c = 0; c < 4; c++) bsv[c] = bias[i0 + tx * 4 + c];
    }

    #pragma unroll
    for (int r = 0; r < 8; r++) {
        float* obase = C + (size_t)(b0 + ty * 8 + r) * F + i0 + tx * 4;
        atomicAdd(obase + 0, acc[r][0] + bsv[0]);
        atomicAdd(obase + 1, acc[r][1] + bsv[1]);
        atomicAdd(obase + 2, acc[r][2] + bsv[2]);
        atomicAdd(obase + 3, acc[r][3] + bsv[3]);
    }
}

// ---------------- K4: per-action gather GEMM, K-split 8 + atomics ----------------
// out[b][i] += sum_{j in kc} W[a][i][j] * p_embed[b][j]
// grid (NACT, 8 kchunks, 2 ihalves), 256 threads.
// CTA tile: 256i x 16m x 64k. Micro 2m x 8i (16 accs).
#define KC 64
__global__ void __launch_bounds__(256)
k_action(const float* __restrict__ W, float* __restrict__ dout)
{
    const int a   = blockIdx.x;
    const int kc  = blockIdx.y;        // k chunk 0..7
    const int ih  = blockIdx.z;        // i half
    const int i0  = ih * 256;
    const int k0g = kc * KC;
    const int beg = g_off[a];
    const int n   = g_off[a + 1] - beg;

    __shared__ float As[16][KC + 4];   // P rows [m][k_local]
    __shared__ float Bs[8][256];       // W chunk [k][i]

    const int t  = threadIdx.x;        // 0..255
    const int ti = t & 31;
    const int tm = t >> 5;
    const int ia = ti * 4;
    const int ib = ti * 4 + 128;

    const float* Wa = W + (size_t)a * F * F + (size_t)i0 * F + k0g;

    for (int m0 = 0; m0 < n; m0 += 16) {
        // ---- stage 16 P rows (local K window) ----
        {
            const int m  = t >> 4;             // 0..15
            const int c4 = t & 15;             // float4 lane (16 per row = 64 floats)
            const int mi = (m0 + m < n) ? (m0 + m) : m0;   // clamp; never written out
            const float* src = g_p_embed + (size_t)g_perm[beg + mi] * F + k0g;
            *(float4*)&As[m][c4 * 4] = *(const float4*)(src + c4 * 4);
        }

        float acc[2][8];
        #pragma unroll
        for (int r = 0; r < 2; r++)
            #pragma unroll
            for (int c = 0; c < 8; c++) acc[r][c] = 0.f;

        // prefetch W chunk 0: row t, k 0..7 of local window
        float4 w0 = *(const float4*)(Wa + (size_t)t * F + 0);
        float4 w1 = *(const float4*)(Wa + (size_t)t * F + 4);
        __syncthreads();   // As staged

        for (int c = 0; c < KC / 8; c++) {
            Bs[0][t] = w0.x; Bs[1][t] = w0.y; Bs[2][t] = w0.z; Bs[3][t] = w0.w;
            Bs[4][t] = w1.x; Bs[5][t] = w1.y; Bs[6][t] = w1.z; Bs[7][t] = w1.w;
            __syncthreads();

            if (c + 1 < KC / 8) {
                const int kn = (c + 1) * 8;
                w0 = *(const float4*)(Wa + (size_t)t * F + kn);
                w1 = *(const float4*)(Wa + (size_t)t * F + kn + 4);
            }

            const int kb = c * 8;
            #pragma unroll
            for (int kk = 0; kk < 8; kk++) {
                const float a0v = As[tm * 2 + 0][kb + kk];
                const float a1v = As[tm * 2 + 1][kb + kk];
                const float4 b0 = *(const float4*)&Bs[kk][ia];
                const float4 b1 = *(const float4*)&Bs[kk][ib];
                acc[0][0] += a0v * b0.x; acc[0][1] += a0v * b0.y;
                acc[0][2] += a0v * b0.z; acc[0][3] += a0v * b0.w;
                acc[0][4] += a0v * b1.x; acc[0][5] += a0v * b1.y;
                acc[0][6] += a0v * b1.z; acc[0][7] += a0v * b1.w;
                acc[1][0] += a1v * b0.x; acc[1][1] += a1v * b0.y;
                acc[1][2] += a1v * b0.z; acc[1][3] += a1v * b0.w;
                acc[1][4] += a1v * b1.x; acc[1][5] += a1v * b1.y;
                acc[1][6] += a1v * b1.z; acc[1][7] += a1v * b1.w;
            }
            __syncthreads();
        }

        // accumulate partials into output
        #pragma unroll
        for (int r = 0; r < 2; r++) {
            const int m = m0 + tm * 2 + r;
            if (m < n) {
                float* obase = dout + (size_t)g_perm[beg + m] * F + i0;
                atomicAdd(obase + ia + 0, acc[r][0]);
                atomicAdd(obase + ia + 1, acc[r][1]);
                atomicAdd(obase + ia + 2, acc[r][2]);
                atomicAdd(obase + ia + 3, acc[r][3]);
                atomicAdd(obase + ib + 0, acc[r][4]);
                atomicAdd(obase + ib + 1, acc[r][5]);
                atomicAdd(obase + ib + 2, acc[r][6]);
                atomicAdd(obase + ib + 3, acc[r][7]);
            }
        }
    }
}

// ---------------- launch ----------------
extern "C" void kernel_launch(void* const* d_in, const int* in_sizes, int n_in,
                              void* d_out, int out_size)
{
    const float* pre   = (const float*)d_in[0];
    const float* eff   = (const float*)d_in[1];
    const int*   act   = (const int*)  d_in[2];
    const float* W     = (const float*)d_in[3];
    const float* pw    = (const float*)d_in[4];
    const float* pb    = (const float*)d_in[5];
    const float* ew    = (const float*)d_in[6];
    const float* eb    = (const float*)d_in[7];
    const float* gamma = (const float*)d_in[8];
    const float* beta  = (const float*)d_in[9];
    float* out = (float*)d_out;

    // zero d_out (2M floats) + g_p_embed (1M floats) = 3M floats = 768K float4
    k_zero<<<(BATCH * F * 3) / (256 * 4), 256>>>(out);
    k_group<<<1, 256>>>(act);
    k_reduce_gn<<<dim3(BATCH, 2), 128>>>(pre, eff, gamma, beta);
    k_embed<<<dim3(F / 64, BATCH / 128, 4), 256>>>(pw, pb, ew, eb, out);
    k_action<<<dim3(NACT, 8, 2), 256>>>(W, out);
}